// round 1
// baseline (speedup 1.0000x reference)
#include <cuda_runtime.h>
#include <math.h>

#define TT 4096
#define DD 2048
#define FF 5632
#define EE 8
#define BM 128
#define BN 128
#define BK 16

typedef unsigned long long ull;

// Static scratch (allocation-free per harness rules)
__device__ int   d_cnt[EE];
__device__ int   d_tok[EE][TT];
__device__ float d_wt[EE][TT];
__device__ float d_H[(size_t)EE * TT * FF];   // 738 MB expert activations

__device__ __forceinline__ void fma2(ull& d, ull a, ull b) {
    asm("fma.rn.f32x2 %0, %1, %2, %0;" : "+l"(d) : "l"(a), "l"(b));
}
__device__ __forceinline__ ull pack2(float lo, float hi) {
    ull d;
    asm("mov.b64 %0, {%1, %2};" : "=l"(d)
        : "r"(__float_as_uint(lo)), "r"(__float_as_uint(hi)));
    return d;
}
__device__ __forceinline__ void unpack2(ull v, float& lo, float& hi) {
    unsigned a, b;
    asm("mov.b64 {%0, %1}, %2;" : "=r"(a), "=r"(b) : "l"(v));
    lo = __uint_as_float(a);
    hi = __uint_as_float(b);
}
__device__ __forceinline__ float gelu_exact(float h) {
    return 0.5f * h * (1.0f + erff(h * 0.70710678118654752440f));
}

// ---------------------------------------------------------------------------
// init: zero output + expert counters
// ---------------------------------------------------------------------------
__global__ void init_kernel(float4* __restrict__ out) {
    size_t i = (size_t)blockIdx.x * blockDim.x + threadIdx.x;
    out[i] = make_float4(0.f, 0.f, 0.f, 0.f);
    if (blockIdx.x == 0 && threadIdx.x < EE) d_cnt[threadIdx.x] = 0;
}

// ---------------------------------------------------------------------------
// gating: 1 warp per token. logits -> softmax -> top2 -> scatter to lists
// ---------------------------------------------------------------------------
__global__ void gate_kernel(const float* __restrict__ x,
                            const float* __restrict__ gw,
                            const float* __restrict__ gb) {
    int t = (int)((blockIdx.x * blockDim.x + threadIdx.x) >> 5);
    int lane = threadIdx.x & 31;
    if (t >= TT) return;
    const float* xr = x + (size_t)t * DD;

    float acc[EE];
#pragma unroll
    for (int e = 0; e < EE; e++) acc[e] = 0.f;

    for (int d = lane; d < DD; d += 32) {
        float xv = __ldg(xr + d);
        const float* g = gw + (size_t)d * EE;
#pragma unroll
        for (int e = 0; e < EE; e++) acc[e] = fmaf(xv, __ldg(g + e), acc[e]);
    }
#pragma unroll
    for (int e = 0; e < EE; e++) {
#pragma unroll
        for (int o = 16; o > 0; o >>= 1)
            acc[e] += __shfl_xor_sync(0xffffffffu, acc[e], o);
    }
    if (lane == 0) {
#pragma unroll
        for (int e = 0; e < EE; e++) acc[e] += gb[e];
        float mx = acc[0];
#pragma unroll
        for (int e = 1; e < EE; e++) mx = fmaxf(mx, acc[e]);
        float p[EE];
        float s = 0.f;
#pragma unroll
        for (int e = 0; e < EE; e++) { p[e] = expf(acc[e] - mx); s += p[e]; }
        float inv = 1.f / s;
        // top-1 (strict > keeps lowest index on ties, matching lax.top_k)
        int i1 = 0; float v1 = p[0];
#pragma unroll
        for (int e = 1; e < EE; e++) if (p[e] > v1) { v1 = p[e]; i1 = e; }
        int i2 = -1; float v2 = -1.f;
#pragma unroll
        for (int e = 0; e < EE; e++)
            if (e != i1 && p[e] > v2) { v2 = p[e]; i2 = e; }

        int pos = atomicAdd(&d_cnt[i1], 1);
        d_tok[i1][pos] = t; d_wt[i1][pos] = v1 * inv;
        pos = atomicAdd(&d_cnt[i2], 1);
        d_tok[i2][pos] = t; d_wt[i2][pos] = v2 * inv;
    }
}

// ---------------------------------------------------------------------------
// GEMM1: H[e, m, :] = gelu( x[tok] @ W1[e] + b1[e] )   (gathered A rows)
// grid: (FF/BN, TT/BM, EE), 256 threads, 8x8 per thread, f32x2 FMA core
// ---------------------------------------------------------------------------
__global__ __launch_bounds__(256) void gemm1_kernel(
    const float* __restrict__ x,
    const float* __restrict__ W1,
    const float* __restrict__ b1) {
    int e = blockIdx.z;
    int ne = d_cnt[e];
    int m0 = blockIdx.y * BM;
    if (m0 >= ne) return;
    int n0 = blockIdx.x * BN;

    __shared__ float As[BK][BM];
    __shared__ float Bs[BK][BN];
    __shared__ int srow[BM];

    int tid = threadIdx.x;
    if (tid < BM) {
        int m = m0 + tid;
        srow[tid] = (m < ne) ? d_tok[e][m] : -1;
    }
    __syncthreads();

    const float* Bp = W1 + (size_t)e * DD * FF + n0;

    ull acc[4][8];
#pragma unroll
    for (int i = 0; i < 4; i++)
#pragma unroll
        for (int j = 0; j < 8; j++) acc[i][j] = 0ULL;

    int tm = (tid >> 4) << 3;
    int tn = (tid & 15) << 3;

    for (int k0 = 0; k0 < DD; k0 += BK) {
        // A tile (gathered rows), transposed into As[k][m]
#pragma unroll
        for (int l = 0; l < 2; l++) {
            int idx = tid + (l << 8);
            int r = idx >> 2;
            int kc = (idx & 3) << 2;
            float4 v = make_float4(0.f, 0.f, 0.f, 0.f);
            int tk = srow[r];
            if (tk >= 0) v = *(const float4*)(x + (size_t)tk * DD + k0 + kc);
            As[kc + 0][r] = v.x; As[kc + 1][r] = v.y;
            As[kc + 2][r] = v.z; As[kc + 3][r] = v.w;
        }
        // B tile
#pragma unroll
        for (int l = 0; l < 2; l++) {
            int idx = tid + (l << 8);
            int kk = idx >> 5;
            int nc = (idx & 31) << 2;
            *(float4*)&Bs[kk][nc] =
                *(const float4*)(Bp + (size_t)(k0 + kk) * FF + nc);
        }
        __syncthreads();
#pragma unroll
        for (int k = 0; k < BK; k++) {
            ulonglong2 aL = *(const ulonglong2*)&As[k][tm];
            ulonglong2 aH = *(const ulonglong2*)&As[k][tm + 4];
            float4 b0 = *(const float4*)&Bs[k][tn];
            float4 b4 = *(const float4*)&Bs[k][tn + 4];
            ull ar[4] = {aL.x, aL.y, aH.x, aH.y};
            ull bb[8];
            bb[0] = pack2(b0.x, b0.x); bb[1] = pack2(b0.y, b0.y);
            bb[2] = pack2(b0.z, b0.z); bb[3] = pack2(b0.w, b0.w);
            bb[4] = pack2(b4.x, b4.x); bb[5] = pack2(b4.y, b4.y);
            bb[6] = pack2(b4.z, b4.z); bb[7] = pack2(b4.w, b4.w);
#pragma unroll
            for (int i = 0; i < 4; i++)
#pragma unroll
                for (int j = 0; j < 8; j++) fma2(acc[i][j], ar[i], bb[j]);
        }
        __syncthreads();
    }

    float bias[8];
#pragma unroll
    for (int j = 0; j < 8; j++) bias[j] = b1[(size_t)e * FF + n0 + tn + j];

#pragma unroll
    for (int i = 0; i < 4; i++) {
        float v0[8], v1[8];
#pragma unroll
        for (int j = 0; j < 8; j++) unpack2(acc[i][j], v0[j], v1[j]);
        int mA = m0 + tm + 2 * i;
        int mB = mA + 1;
        if (mA < ne) {
            float* h = d_H + ((size_t)e * TT + mA) * FF + n0 + tn;
#pragma unroll
            for (int j = 0; j < 8; j++) h[j] = gelu_exact(v0[j] + bias[j]);
        }
        if (mB < ne) {
            float* h = d_H + ((size_t)e * TT + mB) * FF + n0 + tn;
#pragma unroll
            for (int j = 0; j < 8; j++) h[j] = gelu_exact(v1[j] + bias[j]);
        }
    }
}

// ---------------------------------------------------------------------------
// GEMM2: out[tok] += w * ( H[e] @ W2[e] + b2[e] )
// grid: (DD/BN, TT/BM, EE). atomicAdd: a token appears in 2 expert z-slices.
// ---------------------------------------------------------------------------
__global__ __launch_bounds__(256) void gemm2_kernel(
    const float* __restrict__ W2,
    const float* __restrict__ b2,
    float* __restrict__ out) {
    int e = blockIdx.z;
    int ne = d_cnt[e];
    int m0 = blockIdx.y * BM;
    if (m0 >= ne) return;
    int n0 = blockIdx.x * BN;

    __shared__ float As[BK][BM];
    __shared__ float Bs[BK][BN];
    __shared__ int   srow[BM];
    __shared__ float swt[BM];

    int tid = threadIdx.x;
    if (tid < BM) {
        int m = m0 + tid;
        if (m < ne) { srow[tid] = d_tok[e][m]; swt[tid] = d_wt[e][m]; }
        else        { srow[tid] = -1;          swt[tid] = 0.f; }
    }
    __syncthreads();

    const float* Ap = d_H + ((size_t)e * TT + m0) * FF;
    const float* Bp = W2 + (size_t)e * FF * DD + n0;

    ull acc[4][8];
#pragma unroll
    for (int i = 0; i < 4; i++)
#pragma unroll
        for (int j = 0; j < 8; j++) acc[i][j] = 0ULL;

    int tm = (tid >> 4) << 3;
    int tn = (tid & 15) << 3;

    for (int k0 = 0; k0 < FF; k0 += BK) {
#pragma unroll
        for (int l = 0; l < 2; l++) {
            int idx = tid + (l << 8);
            int r = idx >> 2;
            int kc = (idx & 3) << 2;
            // rows >= ne hold stale-but-finite data; results discarded at store
            float4 v = *(const float4*)(Ap + (size_t)r * FF + k0 + kc);
            As[kc + 0][r] = v.x; As[kc + 1][r] = v.y;
            As[kc + 2][r] = v.z; As[kc + 3][r] = v.w;
        }
#pragma unroll
        for (int l = 0; l < 2; l++) {
            int idx = tid + (l << 8);
            int kk = idx >> 5;
            int nc = (idx & 31) << 2;
            *(float4*)&Bs[kk][nc] =
                *(const float4*)(Bp + (size_t)(k0 + kk) * DD + nc);
        }
        __syncthreads();
#pragma unroll
        for (int k = 0; k < BK; k++) {
            ulonglong2 aL = *(const ulonglong2*)&As[k][tm];
            ulonglong2 aH = *(const ulonglong2*)&As[k][tm + 4];
            float4 b0 = *(const float4*)&Bs[k][tn];
            float4 b4 = *(const float4*)&Bs[k][tn + 4];
            ull ar[4] = {aL.x, aL.y, aH.x, aH.y};
            ull bb[8];
            bb[0] = pack2(b0.x, b0.x); bb[1] = pack2(b0.y, b0.y);
            bb[2] = pack2(b0.z, b0.z); bb[3] = pack2(b0.w, b0.w);
            bb[4] = pack2(b4.x, b4.x); bb[5] = pack2(b4.y, b4.y);
            bb[6] = pack2(b4.z, b4.z); bb[7] = pack2(b4.w, b4.w);
#pragma unroll
            for (int i = 0; i < 4; i++)
#pragma unroll
                for (int j = 0; j < 8; j++) fma2(acc[i][j], ar[i], bb[j]);
        }
        __syncthreads();
    }

    float bias[8];
#pragma unroll
    for (int j = 0; j < 8; j++) bias[j] = b2[(size_t)e * DD + n0 + tn + j];

#pragma unroll
    for (int i = 0; i < 4; i++) {
        float v0[8], v1[8];
#pragma unroll
        for (int j = 0; j < 8; j++) unpack2(acc[i][j], v0[j], v1[j]);
        int mA = m0 + tm + 2 * i;
        int mB = mA + 1;
        if (mA < ne) {
            int t = srow[tm + 2 * i];
            float w = swt[tm + 2 * i];
            float* o = out + (size_t)t * DD + n0 + tn;
#pragma unroll
            for (int j = 0; j < 8; j++)
                atomicAdd(o + j, w * (v0[j] + bias[j]));
        }
        if (mB < ne) {
            int t = srow[tm + 2 * i + 1];
            float w = swt[tm + 2 * i + 1];
            float* o = out + (size_t)t * DD + n0 + tn;
#pragma unroll
            for (int j = 0; j < 8; j++)
                atomicAdd(o + j, w * (v1[j] + bias[j]));
        }
    }
}

// ---------------------------------------------------------------------------
extern "C" void kernel_launch(void* const* d_in, const int* in_sizes, int n_in,
                              void* d_out, int out_size) {
    const float* x  = (const float*)d_in[0];
    const float* gw = (const float*)d_in[1];
    const float* gb = (const float*)d_in[2];
    const float* W1 = (const float*)d_in[3];
    const float* b1 = (const float*)d_in[4];
    const float* W2 = (const float*)d_in[5];
    const float* b2 = (const float*)d_in[6];
    float* out = (float*)d_out;

    // TT*DD floats = 8,388,608 -> 2,097,152 float4 -> 8192 blocks x 256
    init_kernel<<<(TT * DD / 4) / 256, 256>>>((float4*)out);
    gate_kernel<<<TT / 8, 256>>>(x, gw, gb);
    gemm1_kernel<<<dim3(FF / BN, TT / BM, EE), 256>>>(x, W1, b1);
    gemm2_kernel<<<dim3(DD / BN, TT / BM, EE), 256>>>(W2, b2, out);
}

// round 3
// speedup vs baseline: 2.8106x; 2.8106x over previous
#include <cuda_runtime.h>
#include <cuda_bf16.h>
#include <math.h>
#include <stdint.h>

#define TT 4096
#define DD 2048
#define FF 5632
#define EE 8

// ---------------------------------------------------------------------------
// Static scratch (allocation-free per harness rules)
// ---------------------------------------------------------------------------
__device__ int   d_cnt[EE];
__device__ int   d_tok[EE][TT];
__device__ float d_wt[EE][TT];
__device__ __nv_bfloat16 d_xh[(size_t)TT * DD];
__device__ __nv_bfloat16 d_xl[(size_t)TT * DD];
__device__ __nv_bfloat16 d_w1h[(size_t)EE * FF * DD];  // [e][f][d] (B^T)
__device__ __nv_bfloat16 d_w1l[(size_t)EE * FF * DD];
__device__ __nv_bfloat16 d_w2h[(size_t)EE * DD * FF];  // [e][d][f] (B^T)
__device__ __nv_bfloat16 d_w2l[(size_t)EE * DD * FF];
__device__ __nv_bfloat16 d_Hh[(size_t)EE * TT * FF];   // [e][pos][f]
__device__ __nv_bfloat16 d_Hl[(size_t)EE * TT * FF];

// ---------------------------------------------------------------------------
// PTX helpers — base-ISA only (no sm_103a-gated features)
// ---------------------------------------------------------------------------
__device__ __forceinline__ uint32_t smem_u32(const void* p) {
    uint32_t a;
    asm("{ .reg .u64 t; cvta.to.shared.u64 t, %1; cvt.u32.u64 %0, t; }"
        : "=r"(a) : "l"(p));
    return a;
}
#define SWZ(o) ((o) ^ (((o) >> 3) & 0x70))

#define CP16(dst, src) \
    asm volatile("cp.async.cg.shared.global [%0], [%1], 16;" \
                 :: "r"(dst), "l"(src))
#define CP16Z(dst, src, sz) \
    asm volatile("cp.async.cg.shared.global [%0], [%1], 16, %2;" \
                 :: "r"(dst), "l"(src), "r"(sz))
#define CP_COMMIT() asm volatile("cp.async.commit_group;" ::: "memory")
#define CP_WAIT0()  asm volatile("cp.async.wait_group 0;" ::: "memory")
#define CP_WAIT1()  asm volatile("cp.async.wait_group 1;" ::: "memory")

__device__ __forceinline__ void ldsm4(uint32_t* r, uint32_t a) {
    asm volatile("ldmatrix.sync.aligned.m8n8.x4.shared.b16 {%0,%1,%2,%3}, [%4];"
                 : "=r"(r[0]), "=r"(r[1]), "=r"(r[2]), "=r"(r[3]) : "r"(a));
}
__device__ __forceinline__ void mma_bf16(float* c, const uint32_t* a,
                                         const uint32_t* b) {
    asm volatile(
        "mma.sync.aligned.m16n8k16.row.col.f32.bf16.bf16.f32 "
        "{%0,%1,%2,%3}, {%4,%5,%6,%7}, {%8,%9}, {%0,%1,%2,%3};"
        : "+f"(c[0]), "+f"(c[1]), "+f"(c[2]), "+f"(c[3])
        : "r"(a[0]), "r"(a[1]), "r"(a[2]), "r"(a[3]), "r"(b[0]), "r"(b[1]));
}
__device__ __forceinline__ float gelu_exact(float h) {
    return 0.5f * h * (1.0f + erff(h * 0.70710678118654752440f));
}

// smem layout: header + 2 buffers x 4 tensors x 16KB
#define OFF_SROW 0
#define OFF_SWT  512
#define OFF_BIAS 1024
#define OFF_TILE 2048
#define TOFF(b, t) (OFF_TILE + (((b) << 2) + (t)) * 16384)
#define SMEM_BYTES (OFF_TILE + 8 * 16384)

// ---------------------------------------------------------------------------
__global__ void init_kernel(float4* __restrict__ out) {
    size_t i = (size_t)blockIdx.x * blockDim.x + threadIdx.x;
    out[i] = make_float4(0.f, 0.f, 0.f, 0.f);
    if (blockIdx.x == 0 && threadIdx.x < EE) d_cnt[threadIdx.x] = 0;
}

// ---------------------------------------------------------------------------
__global__ void gate_kernel(const float* __restrict__ x,
                            const float* __restrict__ gw,
                            const float* __restrict__ gb) {
    int t = (int)((blockIdx.x * blockDim.x + threadIdx.x) >> 5);
    int lane = threadIdx.x & 31;
    if (t >= TT) return;
    const float* xr = x + (size_t)t * DD;

    float acc[EE];
#pragma unroll
    for (int e = 0; e < EE; e++) acc[e] = 0.f;
    for (int d = lane; d < DD; d += 32) {
        float xv = __ldg(xr + d);
        const float* g = gw + (size_t)d * EE;
#pragma unroll
        for (int e = 0; e < EE; e++) acc[e] = fmaf(xv, __ldg(g + e), acc[e]);
    }
#pragma unroll
    for (int e = 0; e < EE; e++) {
#pragma unroll
        for (int o = 16; o > 0; o >>= 1)
            acc[e] += __shfl_xor_sync(0xffffffffu, acc[e], o);
    }
    if (lane == 0) {
#pragma unroll
        for (int e = 0; e < EE; e++) acc[e] += gb[e];
        float mx = acc[0];
#pragma unroll
        for (int e = 1; e < EE; e++) mx = fmaxf(mx, acc[e]);
        float p[EE]; float s = 0.f;
#pragma unroll
        for (int e = 0; e < EE; e++) { p[e] = expf(acc[e] - mx); s += p[e]; }
        float inv = 1.f / s;
        int i1 = 0; float v1 = p[0];
#pragma unroll
        for (int e = 1; e < EE; e++) if (p[e] > v1) { v1 = p[e]; i1 = e; }
        int i2 = -1; float v2 = -1.f;
#pragma unroll
        for (int e = 0; e < EE; e++)
            if (e != i1 && p[e] > v2) { v2 = p[e]; i2 = e; }
        int pos = atomicAdd(&d_cnt[i1], 1);
        d_tok[i1][pos] = t; d_wt[i1][pos] = v1 * inv;
        pos = atomicAdd(&d_cnt[i2], 1);
        d_tok[i2][pos] = t; d_wt[i2][pos] = v2 * inv;
    }
}

// ---------------------------------------------------------------------------
__global__ void convert_x_kernel(const float4* __restrict__ x4) {
    size_t i = (size_t)blockIdx.x * blockDim.x + threadIdx.x;
    float4 v = x4[i];
    __nv_bfloat16 h0 = __float2bfloat16(v.x), h1 = __float2bfloat16(v.y);
    __nv_bfloat16 h2 = __float2bfloat16(v.z), h3 = __float2bfloat16(v.w);
    __nv_bfloat16 l0 = __float2bfloat16(v.x - __bfloat162float(h0));
    __nv_bfloat16 l1 = __float2bfloat16(v.y - __bfloat162float(h1));
    __nv_bfloat16 l2 = __float2bfloat16(v.z - __bfloat162float(h2));
    __nv_bfloat16 l3 = __float2bfloat16(v.w - __bfloat162float(h3));
    *(__nv_bfloat162*)(d_xh + i * 4 + 0) = __halves2bfloat162(h0, h1);
    *(__nv_bfloat162*)(d_xh + i * 4 + 2) = __halves2bfloat162(h2, h3);
    *(__nv_bfloat162*)(d_xl + i * 4 + 0) = __halves2bfloat162(l0, l1);
    *(__nv_bfloat162*)(d_xl + i * 4 + 2) = __halves2bfloat162(l2, l3);
}

// ---------------------------------------------------------------------------
__global__ void transpose_split_kernel(const float* __restrict__ src, int which,
                                       int R, int C) {
    __shared__ float t[32][33];
    int e = blockIdx.z;
    const float* S = src + (size_t)e * R * C;
    __nv_bfloat16* DH = (which ? d_w2h : d_w1h) + (size_t)e * R * C;
    __nv_bfloat16* DL = (which ? d_w2l : d_w1l) + (size_t)e * R * C;
    int c0 = blockIdx.x * 32, r0 = blockIdx.y * 32;
    int tx = threadIdx.x, ty = threadIdx.y;
#pragma unroll
    for (int j = 0; j < 32; j += 8)
        t[ty + j][tx] = S[(size_t)(r0 + ty + j) * C + c0 + tx];
    __syncthreads();
#pragma unroll
    for (int j = 0; j < 32; j += 8) {
        float v = t[tx][ty + j];
        size_t o = (size_t)(c0 + ty + j) * R + r0 + tx;
        __nv_bfloat16 h = __float2bfloat16(v);
        DH[o] = h;
        DL[o] = __float2bfloat16(v - __bfloat162float(h));
    }
}

// ---------------------------------------------------------------------------
// warp-level compute of one K=64 chunk: c += A(128x64) * B(128x64)^T slice
// ---------------------------------------------------------------------------
__device__ __forceinline__ void mma_chunk(float c[4][4][4], uint32_t sAh,
                                          uint32_t sAl, uint32_t sBh,
                                          uint32_t sBl, int wm0, int wn0,
                                          int lid) {
    int mat = lid >> 3, lr = lid & 7;
#pragma unroll
    for (int ks = 0; ks < 4; ks++) {
        uint32_t ah[4][4], al[4][4], bh[4][2], bl[4][2];
#pragma unroll
        for (int i = 0; i < 4; i++) {
            int row = wm0 + i * 16 + ((mat & 1) << 3) + lr;
            int col = ks * 16 + ((mat >> 1) << 3);
            uint32_t off = SWZ((row << 7) + (col << 1));
            ldsm4(ah[i], sAh + off);
            ldsm4(al[i], sAl + off);
        }
#pragma unroll
        for (int jp = 0; jp < 2; jp++) {
            int row = wn0 + jp * 16 + ((mat >> 1) << 3) + lr;
            int col = ks * 16 + ((mat & 1) << 3);
            uint32_t off = SWZ((row << 7) + (col << 1));
            uint32_t t4[4];
            ldsm4(t4, sBh + off);
            bh[jp * 2][0] = t4[0]; bh[jp * 2][1] = t4[1];
            bh[jp * 2 + 1][0] = t4[2]; bh[jp * 2 + 1][1] = t4[3];
            ldsm4(t4, sBl + off);
            bl[jp * 2][0] = t4[0]; bl[jp * 2][1] = t4[1];
            bl[jp * 2 + 1][0] = t4[2]; bl[jp * 2 + 1][1] = t4[3];
        }
#pragma unroll
        for (int i = 0; i < 4; i++)
#pragma unroll
            for (int j = 0; j < 4; j++) {
                mma_bf16(c[i][j], ah[i], bh[j]);
                mma_bf16(c[i][j], al[i], bh[j]);
                mma_bf16(c[i][j], ah[i], bl[j]);
            }
    }
}

// ---------------------------------------------------------------------------
// GEMM1: H[e,m,:] = gelu( x[tok] @ W1[e] + b1[e] ) -> bf16 hi/lo
// ---------------------------------------------------------------------------
__global__ __launch_bounds__(256) void moe_mma1_kernel(
    const float* __restrict__ b1) {
    extern __shared__ char sm[];
    int e = blockIdx.z;
    int ne = d_cnt[e];
    int m0 = blockIdx.y * 128;
    if (m0 >= ne) return;
    int n0 = blockIdx.x * 128;

    int tid = threadIdx.x, wid = tid >> 5, lid = tid & 31;
    uint32_t su = smem_u32(sm);
    int* srow_s = (int*)(sm + OFF_SROW);
    float* bias_s = (float*)(sm + OFF_BIAS);

    if (tid < 128) {
        int m = m0 + tid;
        srow_s[tid] = (m < ne) ? d_tok[e][m] : -1;
        bias_s[tid] = b1[(size_t)e * FF + n0 + tid];
    }
    __syncthreads();

    const __nv_bfloat16* wbh = d_w1h + ((size_t)e * FF + n0) * DD;
    const __nv_bfloat16* wbl = d_w1l + ((size_t)e * FF + n0) * DD;

    float c[4][4][4];
#pragma unroll
    for (int i = 0; i < 4; i++)
#pragma unroll
        for (int j = 0; j < 4; j++)
#pragma unroll
            for (int q = 0; q < 4; q++) c[i][j][q] = 0.f;

    // prefetch chunk 0
#pragma unroll
    for (int r = 0; r < 4; r++) {
        int idx = tid + (r << 8);
        int row = idx >> 3, c8 = idx & 7;
        uint32_t so = SWZ((row << 7) + (c8 << 4));
        int tok = srow_s[row];
        unsigned sz = tok >= 0 ? 16u : 0u;
        size_t oa = (size_t)(tok >= 0 ? tok : 0) * DD + (c8 << 3);
        CP16Z(su + TOFF(0, 0) + so, (const char*)(d_xh + oa), sz);
        CP16Z(su + TOFF(0, 1) + so, (const char*)(d_xl + oa), sz);
        size_t ob = (size_t)row * DD + (c8 << 3);
        CP16(su + TOFF(0, 2) + so, (const char*)(wbh + ob));
        CP16(su + TOFF(0, 3) + so, (const char*)(wbl + ob));
    }
    CP_COMMIT();

    const int NK = DD / 64;
    int wm0 = (wid >> 2) * 64, wn0 = (wid & 3) * 32;
    for (int i = 0; i < NK; i++) {
        if (i + 1 < NK) {
            int nb = (i + 1) & 1;
            int k0 = (i + 1) * 64;
#pragma unroll
            for (int r = 0; r < 4; r++) {
                int idx = tid + (r << 8);
                int row = idx >> 3, c8 = idx & 7;
                uint32_t so = SWZ((row << 7) + (c8 << 4));
                int tok = srow_s[row];
                unsigned sz = tok >= 0 ? 16u : 0u;
                size_t oa = (size_t)(tok >= 0 ? tok : 0) * DD + k0 + (c8 << 3);
                CP16Z(su + TOFF(nb, 0) + so, (const char*)(d_xh + oa), sz);
                CP16Z(su + TOFF(nb, 1) + so, (const char*)(d_xl + oa), sz);
                size_t ob = (size_t)row * DD + k0 + (c8 << 3);
                CP16(su + TOFF(nb, 2) + so, (const char*)(wbh + ob));
                CP16(su + TOFF(nb, 3) + so, (const char*)(wbl + ob));
            }
            CP_COMMIT();
            CP_WAIT1();
        } else {
            CP_WAIT0();
        }
        __syncthreads();
        int b = i & 1;
        mma_chunk(c, su + TOFF(b, 0), su + TOFF(b, 1), su + TOFF(b, 2),
                  su + TOFF(b, 3), wm0, wn0, lid);
        __syncthreads();
    }

    // epilogue: bias + exact gelu + hi/lo split store
    int qr = lid >> 2, qc = (lid & 3) << 1;
#pragma unroll
    for (int i = 0; i < 4; i++) {
#pragma unroll
        for (int h = 0; h < 2; h++) {
            int lrow = wm0 + i * 16 + h * 8 + qr;
            if (m0 + lrow >= ne) continue;
            size_t base = ((size_t)e * TT + m0 + lrow) * FF + n0;
#pragma unroll
            for (int j = 0; j < 4; j++) {
                int colp = wn0 + j * 8 + qc;
                float v0 = c[i][j][h * 2 + 0] + bias_s[colp];
                float v1 = c[i][j][h * 2 + 1] + bias_s[colp + 1];
                float g0 = gelu_exact(v0), g1 = gelu_exact(v1);
                __nv_bfloat16 h0 = __float2bfloat16(g0);
                __nv_bfloat16 h1 = __float2bfloat16(g1);
                __nv_bfloat16 l0 = __float2bfloat16(g0 - __bfloat162float(h0));
                __nv_bfloat16 l1 = __float2bfloat16(g1 - __bfloat162float(h1));
                *(__nv_bfloat162*)(d_Hh + base + colp) = __halves2bfloat162(h0, h1);
                *(__nv_bfloat162*)(d_Hl + base + colp) = __halves2bfloat162(l0, l1);
            }
        }
    }
}

// ---------------------------------------------------------------------------
// GEMM2: out[tok] += w * ( H[e] @ W2[e] + b2[e] )
// ---------------------------------------------------------------------------
__global__ __launch_bounds__(256) void moe_mma2_kernel(
    const float* __restrict__ b2, float* __restrict__ out) {
    extern __shared__ char sm[];
    int e = blockIdx.z;
    int ne = d_cnt[e];
    int m0 = blockIdx.y * 128;
    if (m0 >= ne) return;
    int n0 = blockIdx.x * 128;

    int tid = threadIdx.x, wid = tid >> 5, lid = tid & 31;
    uint32_t su = smem_u32(sm);
    int* srow_s = (int*)(sm + OFF_SROW);
    float* swt_s = (float*)(sm + OFF_SWT);
    float* bias_s = (float*)(sm + OFF_BIAS);

    if (tid < 128) {
        int m = m0 + tid;
        if (m < ne) { srow_s[tid] = d_tok[e][m]; swt_s[tid] = d_wt[e][m]; }
        else        { srow_s[tid] = 0;           swt_s[tid] = 0.f; }
        bias_s[tid] = b2[(size_t)e * DD + n0 + tid];
    }
    __syncthreads();

    const __nv_bfloat16* ah_base = d_Hh + ((size_t)e * TT + m0) * FF;
    const __nv_bfloat16* al_base = d_Hl + ((size_t)e * TT + m0) * FF;
    const __nv_bfloat16* wbh = d_w2h + ((size_t)e * DD + n0) * FF;
    const __nv_bfloat16* wbl = d_w2l + ((size_t)e * DD + n0) * FF;

    float c[4][4][4];
#pragma unroll
    for (int i = 0; i < 4; i++)
#pragma unroll
        for (int j = 0; j < 4; j++)
#pragma unroll
            for (int q = 0; q < 4; q++) c[i][j][q] = 0.f;

#pragma unroll
    for (int r = 0; r < 4; r++) {
        int idx = tid + (r << 8);
        int row = idx >> 3, c8 = idx & 7;
        uint32_t so = SWZ((row << 7) + (c8 << 4));
        size_t oa = (size_t)row * FF + (c8 << 3);
        CP16(su + TOFF(0, 0) + so, (const char*)(ah_base + oa));
        CP16(su + TOFF(0, 1) + so, (const char*)(al_base + oa));
        CP16(su + TOFF(0, 2) + so, (const char*)(wbh + oa));
        CP16(su + TOFF(0, 3) + so, (const char*)(wbl + oa));
    }
    CP_COMMIT();

    const int NK = FF / 64;
    int wm0 = (wid >> 2) * 64, wn0 = (wid & 3) * 32;
    for (int i = 0; i < NK; i++) {
        if (i + 1 < NK) {
            int nb = (i + 1) & 1;
            int k0 = (i + 1) * 64;
#pragma unroll
            for (int r = 0; r < 4; r++) {
                int idx = tid + (r << 8);
                int row = idx >> 3, c8 = idx & 7;
                uint32_t so = SWZ((row << 7) + (c8 << 4));
                size_t oa = (size_t)row * FF + k0 + (c8 << 3);
                CP16(su + TOFF(nb, 0) + so, (const char*)(ah_base + oa));
                CP16(su + TOFF(nb, 1) + so, (const char*)(al_base + oa));
                CP16(su + TOFF(nb, 2) + so, (const char*)(wbh + oa));
                CP16(su + TOFF(nb, 3) + so, (const char*)(wbl + oa));
            }
            CP_COMMIT();
            CP_WAIT1();
        } else {
            CP_WAIT0();
        }
        __syncthreads();
        int b = i & 1;
        mma_chunk(c, su + TOFF(b, 0), su + TOFF(b, 1), su + TOFF(b, 2),
                  su + TOFF(b, 3), wm0, wn0, lid);
        __syncthreads();
    }

    // epilogue: bias + gate weight, atomic add into out
    int qr = lid >> 2, qc = (lid & 3) << 1;
#pragma unroll
    for (int i = 0; i < 4; i++) {
#pragma unroll
        for (int h = 0; h < 2; h++) {
            int lrow = wm0 + i * 16 + h * 8 + qr;
            if (m0 + lrow >= ne) continue;
            int tok = srow_s[lrow];
            float w = swt_s[lrow];
            float* ob = out + (size_t)tok * DD + n0;
#pragma unroll
            for (int j = 0; j < 4; j++) {
                int colp = wn0 + j * 8 + qc;
                float v0 = c[i][j][h * 2 + 0] + bias_s[colp];
                float v1 = c[i][j][h * 2 + 1] + bias_s[colp + 1];
                atomicAdd(ob + colp, w * v0);
                atomicAdd(ob + colp + 1, w * v1);
            }
        }
    }
}

// ---------------------------------------------------------------------------
extern "C" void kernel_launch(void* const* d_in, const int* in_sizes, int n_in,
                              void* d_out, int out_size) {
    const float* x  = (const float*)d_in[0];
    const float* gw = (const float*)d_in[1];
    const float* gb = (const float*)d_in[2];
    const float* W1 = (const float*)d_in[3];
    const float* b1 = (const float*)d_in[4];
    const float* W2 = (const float*)d_in[5];
    const float* b2 = (const float*)d_in[6];
    float* out = (float*)d_out;

    static int configured = 0;
    if (!configured) {
        cudaFuncSetAttribute((const void*)moe_mma1_kernel,
                             cudaFuncAttributeMaxDynamicSharedMemorySize,
                             SMEM_BYTES);
        cudaFuncSetAttribute((const void*)moe_mma2_kernel,
                             cudaFuncAttributeMaxDynamicSharedMemorySize,
                             SMEM_BYTES);
        configured = 1;
    }

    init_kernel<<<(TT * DD / 4) / 256, 256>>>((float4*)out);
    gate_kernel<<<TT / 8, 256>>>(x, gw, gb);
    convert_x_kernel<<<(TT * DD / 4) / 256, 256>>>((const float4*)x);
    transpose_split_kernel<<<dim3(FF / 32, DD / 32, EE), dim3(32, 8)>>>(
        W1, 0, DD, FF);
    transpose_split_kernel<<<dim3(DD / 32, FF / 32, EE), dim3(32, 8)>>>(
        W2, 1, FF, DD);
    moe_mma1_kernel<<<dim3(FF / 128, TT / 128, EE), 256, SMEM_BYTES>>>(b1);
    moe_mma2_kernel<<<dim3(DD / 128, TT / 128, EE), 256, SMEM_BYTES>>>(b2, out);
}

// round 5
// speedup vs baseline: 4.0326x; 1.4348x over previous
#include <cuda_runtime.h>
#include <cuda_fp16.h>
#include <math.h>
#include <stdint.h>

#define TT 4096
#define DD 2048
#define FF 5632
#define EE 8

// ---------------------------------------------------------------------------
// Static scratch (allocation-free per harness rules)
// ---------------------------------------------------------------------------
__device__ int   d_cnt[EE];
__device__ int   d_tok[EE][TT];
__device__ float d_wt[EE][TT];
__device__ __half d_xh[(size_t)TT * DD];
__device__ __half d_xl[(size_t)TT * DD];
__device__ __half d_w1h[(size_t)EE * FF * DD];  // [e][f][d] (B^T)
__device__ __half d_w2h[(size_t)EE * DD * FF];  // [e][d][f] (B^T)
__device__ __half d_Hh[(size_t)EE * TT * FF];   // [e][pos][f]
__device__ __half d_Hl[(size_t)EE * TT * FF];

// ---------------------------------------------------------------------------
// PTX helpers — base-ISA only (no sm_103a-gated features)
// ---------------------------------------------------------------------------
__device__ __forceinline__ uint32_t smem_u32(const void* p) {
    uint32_t a;
    asm("{ .reg .u64 t; cvta.to.shared.u64 t, %1; cvt.u32.u64 %0, t; }"
        : "=r"(a) : "l"(p));
    return a;
}
#define SWZ(o) ((o) ^ (((o) >> 3) & 0x70))

#define CP16(dst, src) \
    asm volatile("cp.async.cg.shared.global [%0], [%1], 16;" \
                 :: "r"(dst), "l"(src))
#define CP16Z(dst, src, sz) \
    asm volatile("cp.async.cg.shared.global [%0], [%1], 16, %2;" \
                 :: "r"(dst), "l"(src), "r"(sz))
#define CP_COMMIT() asm volatile("cp.async.commit_group;" ::: "memory")
#define CP_WAIT0()  asm volatile("cp.async.wait_group 0;" ::: "memory")
#define CP_WAIT1()  asm volatile("cp.async.wait_group 1;" ::: "memory")

__device__ __forceinline__ void ldsm4(uint32_t* r, uint32_t a) {
    asm volatile("ldmatrix.sync.aligned.m8n8.x4.shared.b16 {%0,%1,%2,%3}, [%4];"
                 : "=r"(r[0]), "=r"(r[1]), "=r"(r[2]), "=r"(r[3]) : "r"(a));
}
__device__ __forceinline__ void mma_f16(float* c, const uint32_t* a,
                                        const uint32_t* b) {
    asm volatile(
        "mma.sync.aligned.m16n8k16.row.col.f32.f16.f16.f32 "
        "{%0,%1,%2,%3}, {%4,%5,%6,%7}, {%8,%9}, {%0,%1,%2,%3};"
        : "+f"(c[0]), "+f"(c[1]), "+f"(c[2]), "+f"(c[3])
        : "r"(a[0]), "r"(a[1]), "r"(a[2]), "r"(a[3]), "r"(b[0]), "r"(b[1]));
}
__device__ __forceinline__ float gelu_exact(float h) {
    return 0.5f * h * (1.0f + erff(h * 0.70710678118654752440f));
}

// smem layout: header + 2 buffers x 3 tensors x 16KB = 98KB + header
#define OFF_SROW 0
#define OFF_SWT  512
#define OFF_BIAS 1024
#define OFF_TILE 2048
#define TOFF(b, t) (OFF_TILE + ((b) * 3 + (t)) * 16384)
#define SMEM_BYTES (OFF_TILE + 6 * 16384)

// ---------------------------------------------------------------------------
__global__ void init_kernel(float4* __restrict__ out) {
    size_t i = (size_t)blockIdx.x * blockDim.x + threadIdx.x;
    out[i] = make_float4(0.f, 0.f, 0.f, 0.f);
    if (blockIdx.x == 0 && threadIdx.x < EE) d_cnt[threadIdx.x] = 0;
}

// ---------------------------------------------------------------------------
__global__ void gate_kernel(const float* __restrict__ x,
                            const float* __restrict__ gw,
                            const float* __restrict__ gb) {
    int t = (int)((blockIdx.x * blockDim.x + threadIdx.x) >> 5);
    int lane = threadIdx.x & 31;
    if (t >= TT) return;
    const float* xr = x + (size_t)t * DD;

    float acc[EE];
#pragma unroll
    for (int e = 0; e < EE; e++) acc[e] = 0.f;
    for (int d = lane; d < DD; d += 32) {
        float xv = __ldg(xr + d);
        const float* g = gw + (size_t)d * EE;
#pragma unroll
        for (int e = 0; e < EE; e++) acc[e] = fmaf(xv, __ldg(g + e), acc[e]);
    }
#pragma unroll
    for (int e = 0; e < EE; e++) {
#pragma unroll
        for (int o = 16; o > 0; o >>= 1)
            acc[e] += __shfl_xor_sync(0xffffffffu, acc[e], o);
    }
    if (lane == 0) {
#pragma unroll
        for (int e = 0; e < EE; e++) acc[e] += gb[e];
        float mx = acc[0];
#pragma unroll
        for (int e = 1; e < EE; e++) mx = fmaxf(mx, acc[e]);
        float p[EE]; float s = 0.f;
#pragma unroll
        for (int e = 0; e < EE; e++) { p[e] = expf(acc[e] - mx); s += p[e]; }
        float inv = 1.f / s;
        int i1 = 0; float v1 = p[0];
#pragma unroll
        for (int e = 1; e < EE; e++) if (p[e] > v1) { v1 = p[e]; i1 = e; }
        int i2 = -1; float v2 = -1.f;
#pragma unroll
        for (int e = 0; e < EE; e++)
            if (e != i1 && p[e] > v2) { v2 = p[e]; i2 = e; }
        int pos = atomicAdd(&d_cnt[i1], 1);
        d_tok[i1][pos] = t; d_wt[i1][pos] = v1 * inv;
        pos = atomicAdd(&d_cnt[i2], 1);
        d_tok[i2][pos] = t; d_wt[i2][pos] = v2 * inv;
    }
}

// ---------------------------------------------------------------------------
// x -> (hi, lo) fp16 split
// ---------------------------------------------------------------------------
__global__ void convert_x_kernel(const float4* __restrict__ x4) {
    size_t i = (size_t)blockIdx.x * blockDim.x + threadIdx.x;
    float4 v = x4[i];
    __half h0 = __float2half(v.x), h1 = __float2half(v.y);
    __half h2 = __float2half(v.z), h3 = __float2half(v.w);
    __half l0 = __float2half(v.x - __half2float(h0));
    __half l1 = __float2half(v.y - __half2float(h1));
    __half l2 = __float2half(v.z - __half2float(h2));
    __half l3 = __float2half(v.w - __half2float(h3));
    *(__half2*)(d_xh + i * 4 + 0) = __halves2half2(h0, h1);
    *(__half2*)(d_xh + i * 4 + 2) = __halves2half2(h2, h3);
    *(__half2*)(d_xl + i * 4 + 0) = __halves2half2(l0, l1);
    *(__half2*)(d_xl + i * 4 + 2) = __halves2half2(l2, l3);
}

// ---------------------------------------------------------------------------
// weight transpose to fp16:  src [e][R][C] -> dst [e][C][R]
// ---------------------------------------------------------------------------
__global__ void transpose_kernel(const float* __restrict__ src, int which,
                                 int R, int C) {
    __shared__ float t[32][33];
    int e = blockIdx.z;
    const float* S = src + (size_t)e * R * C;
    __half* DH = (which ? d_w2h : d_w1h) + (size_t)e * R * C;
    int c0 = blockIdx.x * 32, r0 = blockIdx.y * 32;
    int tx = threadIdx.x, ty = threadIdx.y;
#pragma unroll
    for (int j = 0; j < 32; j += 8)
        t[ty + j][tx] = S[(size_t)(r0 + ty + j) * C + c0 + tx];
    __syncthreads();
#pragma unroll
    for (int j = 0; j < 32; j += 8) {
        float v = t[tx][ty + j];
        DH[(size_t)(c0 + ty + j) * R + r0 + tx] = __float2half(v);
    }
}

// ---------------------------------------------------------------------------
// warp compute of one K=64 chunk, 2-pass fp16 split:
// c += Ah(128x64)*Bh^T + Al(128x64)*Bh^T
// ---------------------------------------------------------------------------
__device__ __forceinline__ void mma_chunk(float c[4][4][4], uint32_t sAh,
                                          uint32_t sAl, uint32_t sBh,
                                          int wm0, int wn0, int lid) {
    int mat = lid >> 3, lr = lid & 7;
#pragma unroll
    for (int ks = 0; ks < 4; ks++) {
        uint32_t ah[4][4], al[4][4], bh[4][2];
#pragma unroll
        for (int i = 0; i < 4; i++) {
            int row = wm0 + i * 16 + ((mat & 1) << 3) + lr;
            int col = ks * 16 + ((mat >> 1) << 3);
            uint32_t off = SWZ((row << 7) + (col << 1));
            ldsm4(ah[i], sAh + off);
            ldsm4(al[i], sAl + off);
        }
#pragma unroll
        for (int jp = 0; jp < 2; jp++) {
            int row = wn0 + jp * 16 + ((mat >> 1) << 3) + lr;
            int col = ks * 16 + ((mat & 1) << 3);
            uint32_t off = SWZ((row << 7) + (col << 1));
            uint32_t t4[4];
            ldsm4(t4, sBh + off);
            bh[jp * 2][0] = t4[0]; bh[jp * 2][1] = t4[1];
            bh[jp * 2 + 1][0] = t4[2]; bh[jp * 2 + 1][1] = t4[3];
        }
#pragma unroll
        for (int i = 0; i < 4; i++)
#pragma unroll
            for (int j = 0; j < 4; j++) {
                mma_f16(c[i][j], ah[i], bh[j]);
                mma_f16(c[i][j], al[i], bh[j]);
            }
    }
}

// ---------------------------------------------------------------------------
// GEMM1: H[e,m,:] = gelu( x[tok] @ W1[e] + b1[e] ) -> fp16 hi/lo
// ---------------------------------------------------------------------------
__global__ __launch_bounds__(256, 2) void moe_mma1_kernel(
    const float* __restrict__ b1) {
    extern __shared__ char sm[];
    int e = blockIdx.z;
    int ne = d_cnt[e];
    int m0 = blockIdx.y * 128;
    if (m0 >= ne) return;
    int n0 = blockIdx.x * 128;

    int tid = threadIdx.x, wid = tid >> 5, lid = tid & 31;
    uint32_t su = smem_u32(sm);
    int* srow_s = (int*)(sm + OFF_SROW);
    float* bias_s = (float*)(sm + OFF_BIAS);

    if (tid < 128) {
        int m = m0 + tid;
        srow_s[tid] = (m < ne) ? d_tok[e][m] : -1;
        bias_s[tid] = b1[(size_t)e * FF + n0 + tid];
    }
    __syncthreads();

    const __half* wbh = d_w1h + ((size_t)e * FF + n0) * DD;

    float c[4][4][4];
#pragma unroll
    for (int i = 0; i < 4; i++)
#pragma unroll
        for (int j = 0; j < 4; j++)
#pragma unroll
            for (int q = 0; q < 4; q++) c[i][j][q] = 0.f;

    // prefetch chunk 0
#pragma unroll
    for (int r = 0; r < 4; r++) {
        int idx = tid + (r << 8);
        int row = idx >> 3, c8 = idx & 7;
        uint32_t so = SWZ((row << 7) + (c8 << 4));
        int tok = srow_s[row];
        unsigned sz = tok >= 0 ? 16u : 0u;
        size_t oa = (size_t)(tok >= 0 ? tok : 0) * DD + (c8 << 3);
        CP16Z(su + TOFF(0, 0) + so, (const char*)(d_xh + oa), sz);
        CP16Z(su + TOFF(0, 1) + so, (const char*)(d_xl + oa), sz);
        size_t ob = (size_t)row * DD + (c8 << 3);
        CP16(su + TOFF(0, 2) + so, (const char*)(wbh + ob));
    }
    CP_COMMIT();

    const int NK = DD / 64;
    int wm0 = (wid >> 2) * 64, wn0 = (wid & 3) * 32;
    for (int i = 0; i < NK; i++) {
        if (i + 1 < NK) {
            int nb = (i + 1) & 1;
            int k0 = (i + 1) * 64;
#pragma unroll
            for (int r = 0; r < 4; r++) {
                int idx = tid + (r << 8);
                int row = idx >> 3, c8 = idx & 7;
                uint32_t so = SWZ((row << 7) + (c8 << 4));
                int tok = srow_s[row];
                unsigned sz = tok >= 0 ? 16u : 0u;
                size_t oa = (size_t)(tok >= 0 ? tok : 0) * DD + k0 + (c8 << 3);
                CP16Z(su + TOFF(nb, 0) + so, (const char*)(d_xh + oa), sz);
                CP16Z(su + TOFF(nb, 1) + so, (const char*)(d_xl + oa), sz);
                size_t ob = (size_t)row * DD + k0 + (c8 << 3);
                CP16(su + TOFF(nb, 2) + so, (const char*)(wbh + ob));
            }
            CP_COMMIT();
            CP_WAIT1();
        } else {
            CP_WAIT0();
        }
        __syncthreads();
        int b = i & 1;
        mma_chunk(c, su + TOFF(b, 0), su + TOFF(b, 1), su + TOFF(b, 2),
                  wm0, wn0, lid);
        __syncthreads();
    }

    // epilogue: bias + exact gelu + fp16 hi/lo split store
    int qr = lid >> 2, qc = (lid & 3) << 1;
#pragma unroll
    for (int i = 0; i < 4; i++) {
#pragma unroll
        for (int h = 0; h < 2; h++) {
            int lrow = wm0 + i * 16 + h * 8 + qr;
            if (m0 + lrow >= ne) continue;
            size_t base = ((size_t)e * TT + m0 + lrow) * FF + n0;
#pragma unroll
            for (int j = 0; j < 4; j++) {
                int colp = wn0 + j * 8 + qc;
                float v0 = c[i][j][h * 2 + 0] + bias_s[colp];
                float v1 = c[i][j][h * 2 + 1] + bias_s[colp + 1];
                float g0 = gelu_exact(v0), g1 = gelu_exact(v1);
                __half h0 = __float2half(g0);
                __half h1 = __float2half(g1);
                __half l0 = __float2half(g0 - __half2float(h0));
                __half l1 = __float2half(g1 - __half2float(h1));
                *(__half2*)(d_Hh + base + colp) = __halves2half2(h0, h1);
                *(__half2*)(d_Hl + base + colp) = __halves2half2(l0, l1);
            }
        }
    }
}

// ---------------------------------------------------------------------------
// GEMM2: out[tok] += w * ( H[e] @ W2[e] + b2[e] )
// ---------------------------------------------------------------------------
__global__ __launch_bounds__(256, 2) void moe_mma2_kernel(
    const float* __restrict__ b2, float* __restrict__ out) {
    extern __shared__ char sm[];
    int e = blockIdx.z;
    int ne = d_cnt[e];
    int m0 = blockIdx.y * 128;
    if (m0 >= ne) return;
    int n0 = blockIdx.x * 128;

    int tid = threadIdx.x, wid = tid >> 5, lid = tid & 31;
    uint32_t su = smem_u32(sm);
    int* srow_s = (int*)(sm + OFF_SROW);
    float* swt_s = (float*)(sm + OFF_SWT);
    float* bias_s = (float*)(sm + OFF_BIAS);

    if (tid < 128) {
        int m = m0 + tid;
        if (m < ne) { srow_s[tid] = d_tok[e][m]; swt_s[tid] = d_wt[e][m]; }
        else        { srow_s[tid] = 0;           swt_s[tid] = 0.f; }
        bias_s[tid] = b2[(size_t)e * DD + n0 + tid];
    }
    __syncthreads();

    const __half* ah_base = d_Hh + ((size_t)e * TT + m0) * FF;
    const __half* al_base = d_Hl + ((size_t)e * TT + m0) * FF;
    const __half* wbh = d_w2h + ((size_t)e * DD + n0) * FF;

    float c[4][4][4];
#pragma unroll
    for (int i = 0; i < 4; i++)
#pragma unroll
        for (int j = 0; j < 4; j++)
#pragma unroll
            for (int q = 0; q < 4; q++) c[i][j][q] = 0.f;

#pragma unroll
    for (int r = 0; r < 4; r++) {
        int idx = tid + (r << 8);
        int row = idx >> 3, c8 = idx & 7;
        uint32_t so = SWZ((row << 7) + (c8 << 4));
        size_t oa = (size_t)row * FF + (c8 << 3);
        CP16(su + TOFF(0, 0) + so, (const char*)(ah_base + oa));
        CP16(su + TOFF(0, 1) + so, (const char*)(al_base + oa));
        CP16(su + TOFF(0, 2) + so, (const char*)(wbh + oa));
    }
    CP_COMMIT();

    const int NK = FF / 64;
    int wm0 = (wid >> 2) * 64, wn0 = (wid & 3) * 32;
    for (int i = 0; i < NK; i++) {
        if (i + 1 < NK) {
            int nb = (i + 1) & 1;
            int k0 = (i + 1) * 64;
#pragma unroll
            for (int r = 0; r < 4; r++) {
                int idx = tid + (r << 8);
                int row = idx >> 3, c8 = idx & 7;
                uint32_t so = SWZ((row << 7) + (c8 << 4));
                size_t oa = (size_t)row * FF + k0 + (c8 << 3);
                CP16(su + TOFF(nb, 0) + so, (const char*)(ah_base + oa));
                CP16(su + TOFF(nb, 1) + so, (const char*)(al_base + oa));
                CP16(su + TOFF(nb, 2) + so, (const char*)(wbh + oa));
            }
            CP_COMMIT();
            CP_WAIT1();
        } else {
            CP_WAIT0();
        }
        __syncthreads();
        int b = i & 1;
        mma_chunk(c, su + TOFF(b, 0), su + TOFF(b, 1), su + TOFF(b, 2),
                  wm0, wn0, lid);
        __syncthreads();
    }

    // epilogue: bias + gate weight, atomic add into out
    int qr = lid >> 2, qc = (lid & 3) << 1;
#pragma unroll
    for (int i = 0; i < 4; i++) {
#pragma unroll
        for (int h = 0; h < 2; h++) {
            int lrow = wm0 + i * 16 + h * 8 + qr;
            if (m0 + lrow >= ne) continue;
            int tok = srow_s[lrow];
            float w = swt_s[lrow];
            float* ob = out + (size_t)tok * DD + n0;
#pragma unroll
            for (int j = 0; j < 4; j++) {
                int colp = wn0 + j * 8 + qc;
                float v0 = c[i][j][h * 2 + 0] + bias_s[colp];
                float v1 = c[i][j][h * 2 + 1] + bias_s[colp + 1];
                atomicAdd(ob + colp, w * v0);
                atomicAdd(ob + colp + 1, w * v1);
            }
        }
    }
}

// ---------------------------------------------------------------------------
extern "C" void kernel_launch(void* const* d_in, const int* in_sizes, int n_in,
                              void* d_out, int out_size) {
    const float* x  = (const float*)d_in[0];
    const float* gw = (const float*)d_in[1];
    const float* gb = (const float*)d_in[2];
    const float* W1 = (const float*)d_in[3];
    const float* b1 = (const float*)d_in[4];
    const float* W2 = (const float*)d_in[5];
    const float* b2 = (const float*)d_in[6];
    float* out = (float*)d_out;

    static int configured = 0;
    if (!configured) {
        cudaFuncSetAttribute((const void*)moe_mma1_kernel,
                             cudaFuncAttributeMaxDynamicSharedMemorySize,
                             SMEM_BYTES);
        cudaFuncSetAttribute((const void*)moe_mma2_kernel,
                             cudaFuncAttributeMaxDynamicSharedMemorySize,
                             SMEM_BYTES);
        configured = 1;
    }

    init_kernel<<<(TT * DD / 4) / 256, 256>>>((float4*)out);
    gate_kernel<<<TT / 8, 256>>>(x, gw, gb);
    convert_x_kernel<<<(TT * DD / 4) / 256, 256>>>((const float4*)x);
    transpose_kernel<<<dim3(FF / 32, DD / 32, EE), dim3(32, 8)>>>(W1, 0, DD, FF);
    transpose_kernel<<<dim3(DD / 32, FF / 32, EE), dim3(32, 8)>>>(W2, 1, FF, DD);
    moe_mma1_kernel<<<dim3(FF / 128, TT / 128, EE), 256, SMEM_BYTES>>>(b1);
    moe_mma2_kernel<<<dim3(DD / 128, TT / 128, EE), 256, SMEM_BYTES>>>(b2, out);
}